// round 15
// baseline (speedup 1.0000x reference)
#include <cuda_runtime.h>
#include <math.h>
#include <stdint.h>

#define BB 8
#define DD 256
#define NN 2048
#define NH 4
#define HD 64
#define QTILE 128

typedef unsigned long long u64;
typedef unsigned int u32;

// Scratch. g_q/g_k TRANSPOSED per-head [b][h][tok][dd] (tf32 bits, q pre-scaled);
// g_v natural [b][ch][tok] (tf32 bits); g_x natural fp32.
__device__ float g_q[BB*DD*NN];
__device__ float g_k[BB*DD*NN];
__device__ float g_v[BB*DD*NN];
__device__ float g_x[BB*DD*NN];

__device__ __forceinline__ u32 f2tf32(float x) {
    u32 r; asm("cvt.rna.tf32.f32 %0, %1;" : "=r"(r) : "f"(x)); return r;
}
__device__ __forceinline__ u32 smem_u32(const void* p) {
    u32 a; asm("{ .reg .u64 t; cvta.to.shared.u64 t, %1; cvt.u32.u64 %0, t; }" : "=r"(a) : "l"(p));
    return a;
}
__device__ __forceinline__ void mma_tf32(float c[4], u32 a0, u32 a1, u32 a2, u32 a3,
                                         u32 b0, u32 b1) {
    asm volatile("mma.sync.aligned.m16n8k8.row.col.f32.tf32.tf32.f32 "
        "{%0,%1,%2,%3}, {%4,%5,%6,%7}, {%8,%9}, {%0,%1,%2,%3};"
        : "+f"(c[0]), "+f"(c[1]), "+f"(c[2]), "+f"(c[3])
        : "r"(a0), "r"(a1), "r"(a2), "r"(a3), "r"(b0), "r"(b1));
}
#define LDSM4(r, a) asm volatile( \
    "ldmatrix.sync.aligned.m8n8.x4.shared.b16 {%0,%1,%2,%3}, [%4];" \
    : "=r"((r)[0]), "=r"((r)[1]), "=r"((r)[2]), "=r"((r)[3]) : "r"(a))
#define STS2(a, x, y) asm volatile( \
    "st.shared.v2.b32 [%0], {%1,%2};" :: "r"(a), "r"(x), "r"(y) : "memory")
#define STS4(a, x, y, z, w_) asm volatile( \
    "st.shared.v4.b32 [%0], {%1,%2,%3,%4};" :: "r"(a), "r"(x), "r"(y), "r"(z), "r"(w_) : "memory")
#define CPA16(dst, src) asm volatile( \
    "cp.async.cg.shared.global [%0], [%1], 16;" :: "r"(dst), "l"(src) : "memory")
#define CPA_COMMIT() asm volatile("cp.async.commit_group;" ::: "memory")
#define CPA_WAIT0()  asm volatile("cp.async.wait_group 0;" ::: "memory")
#define CPA_WAIT1()  asm volatile("cp.async.wait_group 1;" ::: "memory")

// ---------------------------------------------------------------------------
// Merged tf32 mma projection for q/k/v. blockIdx.z = p*BB + b, p in {0,1,2}.
// (unchanged from R13 build)
// ---------------------------------------------------------------------------
__global__ __launch_bounds__(256, 2) void qkv_proj(
    const float* __restrict__ Wq, const float* __restrict__ bq, const float* __restrict__ Xq,
    const float* __restrict__ Wk, const float* __restrict__ bk, const float* __restrict__ Xk,
    const float* __restrict__ Wv, const float* __restrict__ bv, const float* __restrict__ Xv,
    float* __restrict__ Yq, float* __restrict__ Yk, float* __restrict__ Yv)
{
    extern __shared__ u32 psm[];
    const u32 sbase = smem_u32(psm);
    const u32 Ao = 0;
    const u32 Bo = 32768;

    const int t = threadIdx.x;
    const int w = t >> 5, lane = t & 31;
    const int wm = w >> 1, wn = w & 1;
    const int gid = lane >> 2, tig = lane & 3;
    const int p  = blockIdx.z >> 3;
    const int b  = blockIdx.z & 7;
    const int o0 = blockIdx.y * 128;
    const int n0 = blockIdx.x * 64;

    const float *W, *bias, *X;
    float* Y;
    if (p == 0)      { W = Wq; bias = bq; X = Xq; Y = Yq; }
    else if (p == 1) { W = Wk; bias = bk; X = Xk; Y = Yk; }
    else             { W = Wv; bias = bv; X = Xv; Y = Yv; }

    const int arow0 = wm * 32 + (lane & 15);
    const int ahi = lane >> 4;
    const int brow8 = ((lane >> 4) << 3) + (lane & 7);
    const int bhi = (lane >> 3) & 1;

    const float* Xb = X + (size_t)b * DD * NN;

    float oc[2][4][4];
#pragma unroll
    for (int mi = 0; mi < 2; mi++)
#pragma unroll
        for (int nb = 0; nb < 4; nb++)
#pragma unroll
            for (int e = 0; e < 4; e++) oc[mi][nb][e] = 0.f;

    for (int kc = 0; kc < DD; kc += 64) {
        __syncthreads();
#pragma unroll
        for (int i = 0; i < 8; i++) {
            int idx = t + i * 256;
            int row = idx >> 4, c = idx & 15;
            float4 wv = *(const float4*)&W[(size_t)(o0 + row) * DD + kc + c * 4];
            u32 a = sbase + Ao + row * 256 + ((c ^ (row & 7)) << 4);
            STS4(a, f2tf32(wv.x), f2tf32(wv.y), f2tf32(wv.z), f2tf32(wv.w));
        }
#pragma unroll
        for (int i = 0; i < 4; i++) {
            int idx = t + i * 256;
            int tok = idx & 63, kq = idx >> 6;
            const float* src = Xb + (size_t)(kc + kq * 4) * NN + n0 + tok;
            u32 v0 = f2tf32(src[0]);
            u32 v1 = f2tf32(src[NN]);
            u32 v2 = f2tf32(src[2 * NN]);
            u32 v3 = f2tf32(src[3 * NN]);
            u32 a = sbase + Bo + tok * 256 + ((kq ^ (tok & 7)) << 4);
            STS4(a, v0, v1, v2, v3);
        }
        __syncthreads();

#pragma unroll
        for (int ks = 0; ks < 8; ks++) {
            u32 A0[4], A1[4];
            {
                int r = arow0;
                u32 a = sbase + Ao + r * 256 + (((ks * 2 + ahi) ^ (r & 7)) << 4);
                LDSM4(A0, a);
                r = arow0 + 16;
                a = sbase + Ao + r * 256 + (((ks * 2 + ahi) ^ (r & 7)) << 4);
                LDSM4(A1, a);
            }
#pragma unroll
            for (int nbp = 0; nbp < 2; nbp++) {
                int rr = wn * 32 + nbp * 16 + brow8;
                u32 ab = sbase + Bo + rr * 256 + (((ks * 2 + bhi) ^ (rr & 7)) << 4);
                u32 B[4]; LDSM4(B, ab);
                mma_tf32(oc[0][nbp*2],   A0[0], A0[1], A0[2], A0[3], B[0], B[1]);
                mma_tf32(oc[1][nbp*2],   A1[0], A1[1], A1[2], A1[3], B[0], B[1]);
                mma_tf32(oc[0][nbp*2+1], A0[0], A0[1], A0[2], A0[3], B[2], B[3]);
                mma_tf32(oc[1][nbp*2+1], A1[0], A1[1], A1[2], A1[3], B[2], B[3]);
            }
        }
    }

    const float scl = (p == 0) ? 0.125f : 1.0f;
    float bv2[2][2];
#pragma unroll
    for (int mi = 0; mi < 2; mi++) {
        bv2[mi][0] = bias[o0 + wm * 32 + mi * 16 + gid];
        bv2[mi][1] = bias[o0 + wm * 32 + mi * 16 + gid + 8];
    }
#pragma unroll
    for (int mi = 0; mi < 2; mi++)
#pragma unroll
    for (int nb = 0; nb < 4; nb++) {
        int token = n0 + wn * 32 + nb * 8 + tig * 2;
        u32 t0 = f2tf32((oc[mi][nb][0] + bv2[mi][0]) * scl);
        u32 t1 = f2tf32((oc[mi][nb][1] + bv2[mi][0]) * scl);
        u32 t2 = f2tf32((oc[mi][nb][2] + bv2[mi][1]) * scl);
        u32 t3 = f2tf32((oc[mi][nb][3] + bv2[mi][1]) * scl);
        int o = o0 + wm * 32 + mi * 16 + gid;
        if (p < 2) {
            {
                float* d = Y + (((size_t)b * NH + (o & 3)) * NN + token) * HD + (o >> 2);
                d[0]  = __uint_as_float(t0);
                d[HD] = __uint_as_float(t1);
            }
            {
                int o2 = o + 8;
                float* d = Y + (((size_t)b * NH + (o2 & 3)) * NN + token) * HD + (o2 >> 2);
                d[0]  = __uint_as_float(t2);
                d[HD] = __uint_as_float(t3);
            }
        } else {
            *(float2*)&Y[((size_t)b * DD + o) * NN + token] =
                make_float2(__uint_as_float(t0), __uint_as_float(t1));
            *(float2*)&Y[((size_t)b * DD + o + 8) * NN + token] =
                make_float2(__uint_as_float(t2), __uint_as_float(t3));
        }
    }
}

// ---------------------------------------------------------------------------
// 3xTF32 output projection (fp32-accurate) — unchanged from R13 build.
// ---------------------------------------------------------------------------
__global__ __launch_bounds__(256, 2) void proj_out3(
    const float* __restrict__ W, const float* __restrict__ bias,
    const float* __restrict__ X, float* __restrict__ Y)
{
    extern __shared__ u32 psm[];
    const u32 sbase = smem_u32(psm);
    const u32 Ahi = 0, Alo = 32768, Bhi = 65536, Blo = 81920;

    const int t = threadIdx.x;
    const int w = t >> 5, lane = t & 31;
    const int wm = w >> 1, wn = w & 1;
    const int gid = lane >> 2, tig = lane & 3;
    const int b  = blockIdx.z;
    const int o0 = blockIdx.y * 128;
    const int n0 = blockIdx.x * 64;

    const int arow0 = wm * 32 + (lane & 15);
    const int ahi = lane >> 4;
    const int brow8 = ((lane >> 4) << 3) + (lane & 7);
    const int bhi = (lane >> 3) & 1;

    const float* Xb = X + (size_t)b * DD * NN;

    float oc[2][4][4];
#pragma unroll
    for (int mi = 0; mi < 2; mi++)
#pragma unroll
        for (int nb = 0; nb < 4; nb++)
#pragma unroll
            for (int e = 0; e < 4; e++) oc[mi][nb][e] = 0.f;

    for (int kc = 0; kc < DD; kc += 64) {
        __syncthreads();
#pragma unroll
        for (int i = 0; i < 8; i++) {
            int idx = t + i * 256;
            int row = idx >> 4, c = idx & 15;
            float4 wv = *(const float4*)&W[(size_t)(o0 + row) * DD + kc + c * 4];
            u32 h0 = f2tf32(wv.x), h1 = f2tf32(wv.y), h2 = f2tf32(wv.z), h3 = f2tf32(wv.w);
            u32 l0 = f2tf32(wv.x - __uint_as_float(h0));
            u32 l1 = f2tf32(wv.y - __uint_as_float(h1));
            u32 l2 = f2tf32(wv.z - __uint_as_float(h2));
            u32 l3 = f2tf32(wv.w - __uint_as_float(h3));
            u32 off = row * 256 + ((c ^ (row & 7)) << 4);
            STS4(sbase + Ahi + off, h0, h1, h2, h3);
            STS4(sbase + Alo + off, l0, l1, l2, l3);
        }
#pragma unroll
        for (int i = 0; i < 4; i++) {
            int idx = t + i * 256;
            int tok = idx & 63, kq = idx >> 6;
            const float* src = Xb + (size_t)(kc + kq * 4) * NN + n0 + tok;
            float x0 = src[0], x1 = src[NN], x2 = src[2 * NN], x3 = src[3 * NN];
            u32 h0 = f2tf32(x0), h1 = f2tf32(x1), h2 = f2tf32(x2), h3 = f2tf32(x3);
            u32 l0 = f2tf32(x0 - __uint_as_float(h0));
            u32 l1 = f2tf32(x1 - __uint_as_float(h1));
            u32 l2 = f2tf32(x2 - __uint_as_float(h2));
            u32 l3 = f2tf32(x3 - __uint_as_float(h3));
            u32 off = tok * 256 + ((kq ^ (tok & 7)) << 4);
            STS4(sbase + Bhi + off, h0, h1, h2, h3);
            STS4(sbase + Blo + off, l0, l1, l2, l3);
        }
        __syncthreads();

        const u32 Ap[3] = {Ahi, Alo, Ahi};
        const u32 Bp[3] = {Bhi, Bhi, Blo};
#pragma unroll
        for (int pass = 0; pass < 3; pass++) {
#pragma unroll
            for (int ks = 0; ks < 8; ks++) {
                u32 A0[4], A1[4];
                {
                    int r = arow0;
                    u32 a = sbase + Ap[pass] + r * 256 + (((ks * 2 + ahi) ^ (r & 7)) << 4);
                    LDSM4(A0, a);
                    r = arow0 + 16;
                    a = sbase + Ap[pass] + r * 256 + (((ks * 2 + ahi) ^ (r & 7)) << 4);
                    LDSM4(A1, a);
                }
#pragma unroll
                for (int nbp = 0; nbp < 2; nbp++) {
                    int rr = wn * 32 + nbp * 16 + brow8;
                    u32 ab = sbase + Bp[pass] + rr * 256 + (((ks * 2 + bhi) ^ (rr & 7)) << 4);
                    u32 B[4]; LDSM4(B, ab);
                    mma_tf32(oc[0][nbp*2],   A0[0], A0[1], A0[2], A0[3], B[0], B[1]);
                    mma_tf32(oc[1][nbp*2],   A1[0], A1[1], A1[2], A1[3], B[0], B[1]);
                    mma_tf32(oc[0][nbp*2+1], A0[0], A0[1], A0[2], A0[3], B[2], B[3]);
                    mma_tf32(oc[1][nbp*2+1], A1[0], A1[1], A1[2], A1[3], B[2], B[3]);
                }
            }
        }
    }

    float bv[2][2];
#pragma unroll
    for (int mi = 0; mi < 2; mi++) {
        bv[mi][0] = bias[o0 + wm * 32 + mi * 16 + gid];
        bv[mi][1] = bias[o0 + wm * 32 + mi * 16 + gid + 8];
    }
#pragma unroll
    for (int mi = 0; mi < 2; mi++)
#pragma unroll
    for (int nb = 0; nb < 4; nb++) {
        int token = n0 + wn * 32 + nb * 8 + tig * 2;
        int o = o0 + wm * 32 + mi * 16 + gid;
        *(float2*)&Y[((size_t)b * DD + o) * NN + token] =
            make_float2(oc[mi][nb][0] + bv[mi][0], oc[mi][nb][1] + bv[mi][0]);
        *(float2*)&Y[((size_t)b * DD + o + 8) * NN + token] =
            make_float2(oc[mi][nb][2] + bv[mi][1], oc[mi][nb][3] + bv[mi][1]);
    }
}

// ---------------------------------------------------------------------------
// mma.sync tf32 flash attention v14: 256 threads, 8 warps (warp = 16 q rows,
// all 64 cols), Q fragments loaded DIRECTLY from global into registers,
// KTILE=64 double-buffered cp.async.
// SMEM bytes: K2[64x64]@0/16384, V2[64x64]@32768/49152, P[128x64]@65536,
//             maskf[2048]@98304. Total 106496. 2 CTAs/SM.
// ---------------------------------------------------------------------------
__global__ __launch_bounds__(256, 2) void attn_mma(const int* __restrict__ mask)
{
    extern __shared__ u32 smu[];
    const u32 sbase = smem_u32(smu);
    const u32 Kob[2] = {0u, 16384u};
    const u32 Vob[2] = {32768u, 49152u};
    const u32 Po = 65536;
    float* sMask = (float*)(smu + 24576);   // byte 98304

    const int t = threadIdx.x;
    const int w = t >> 5, lane = t & 31;
    const int gid = lane >> 2, tig = lane & 3;
    const int b = blockIdx.z, h = blockIdx.y;
    const int q0 = blockIdx.x * QTILE;

    const int arow0 = w * 16 + (lane & 15);       // P A-frag rows
    const int ahi = lane >> 4;
    const int brow8 = ((lane >> 4) << 3) + (lane & 7);
    const int bhi = (lane >> 3) & 1;

    const float* qb = g_q + (((size_t)b * NH + h) * NN + q0) * HD;
    const float* kb0 = g_k + (((size_t)b * NH + h) * NN) * HD;
    const float* vb0 = g_v + ((size_t)b * DD + h) * NN;
    const int* mb_ = mask + (size_t)b * NN;

    // ---- prologue: K0/V0 fills (cp.async) + mask fill ----
#pragma unroll
    for (int i = 0; i < 4; i++) {
        int idx = t + i * 256;
        int row = idx >> 4, c = idx & 15;
        u32 a = sbase + Kob[0] + row * 256 + ((c ^ (row & 7)) << 4);
        CPA16(a, kb0 + (size_t)row * HD + c * 4);
    }
#pragma unroll
    for (int i = 0; i < 4; i++) {
        int idx = t + i * 256;
        int dd = idx >> 4, c = idx & 15;
        u32 a = sbase + Vob[0] + dd * 256 + ((c ^ (dd & 7)) << 4);
        CPA16(a, vb0 + (size_t)dd * (NH * NN) + c * 4);
    }
#pragma unroll
    for (int i = 0; i < 8; i++) {
        int j = t + i * 256;
        sMask[j] = (float)mb_[j];
    }
    CPA_COMMIT();

    // ---- Q fragments: direct global loads into m16n8k8 A-frag layout ----
    // a0=(gid, ks*8+tig), a1=(gid+8, ..), a2=(gid, ks*8+tig+4), a3=(gid+8, ..+4)
    u32 qf[8][4];
    {
        const float* qr0 = qb + (size_t)(w * 16 + gid) * HD;
        const float* qr1 = qr0 + 8 * HD;
#pragma unroll
        for (int ks = 0; ks < 8; ks++) {
            qf[ks][0] = __float_as_uint(qr0[ks * 8 + tig]);
            qf[ks][1] = __float_as_uint(qr1[ks * 8 + tig]);
            qf[ks][2] = __float_as_uint(qr0[ks * 8 + tig + 4]);
            qf[ks][3] = __float_as_uint(qr1[ks * 8 + tig + 4]);
        }
    }

    float qmf[2];
    qmf[0] = (float)mb_[q0 + w * 16 + gid];
    qmf[1] = (float)mb_[q0 + w * 16 + gid + 8];

    float oc[8][4];
#pragma unroll
    for (int nb = 0; nb < 8; nb++)
#pragma unroll
        for (int e = 0; e < 4; e++) oc[nb][e] = 0.f;
    float lsum[2] = {0.f, 0.f};

    for (int it = 0; it < 32; it++) {
        const int k0 = it * 64;
        const int cur = it & 1;
        __syncthreads();   // closes prev-iter reads of the buffer we refill
        if (it + 1 < 32) {
            const int nxt = 1 - cur;
            const int k0n = k0 + 64;
#pragma unroll
            for (int i = 0; i < 4; i++) {
                int idx = t + i * 256;
                int row = idx >> 4, c = idx & 15;
                u32 a = sbase + Kob[nxt] + row * 256 + ((c ^ (row & 7)) << 4);
                CPA16(a, kb0 + (size_t)(k0n + row) * HD + c * 4);
            }
#pragma unroll
            for (int i = 0; i < 4; i++) {
                int idx = t + i * 256;
                int dd = idx >> 4, c = idx & 15;
                u32 a = sbase + Vob[nxt] + dd * 256 + ((c ^ (dd & 7)) << 4);
                CPA16(a, vb0 + (size_t)dd * (NH * NN) + k0n + c * 4);
            }
            CPA_COMMIT();
            CPA_WAIT1();
        } else {
            CPA_WAIT0();
        }
        __syncthreads();   // tile `it` (and mask/Q-region writes) visible

        // ---- S = Q K^T (warp: 16 q x 64 k; Q from registers) ----
        float sc[8][4];
#pragma unroll
        for (int nb = 0; nb < 8; nb++)
#pragma unroll
            for (int e = 0; e < 4; e++) sc[nb][e] = 0.f;
#pragma unroll
        for (int ks = 0; ks < 8; ks++) {
#pragma unroll
            for (int nbp = 0; nbp < 4; nbp++) {
                int rr = nbp * 16 + brow8;
                u32 ab = sbase + Kob[cur] + rr * 256 + (((ks * 2 + bhi) ^ (rr & 7)) << 4);
                u32 B[4]; LDSM4(B, ab);
                mma_tf32(sc[nbp*2],   qf[ks][0], qf[ks][1], qf[ks][2], qf[ks][3], B[0], B[1]);
                mma_tf32(sc[nbp*2+1], qf[ks][0], qf[ks][1], qf[ks][2], qf[ks][3], B[2], B[3]);
            }
        }

        // ---- softmax (no-max, multiply-mask), P -> sP ----
#pragma unroll
        for (int nb = 0; nb < 8; nb++) {
            int col0 = nb * 8 + tig * 2;
            float km0 = sMask[k0 + col0], km1 = sMask[k0 + col0 + 1];
            float e0 = __expf(sc[nb][0]) * qmf[0] * km0;
            float e1 = __expf(sc[nb][1]) * qmf[0] * km1;
            float e2 = __expf(sc[nb][2]) * qmf[1] * km0;
            float e3 = __expf(sc[nb][3]) * qmf[1] * km1;
            lsum[0] += e0 + e1;
            lsum[1] += e2 + e3;
            int ch = col0 >> 2;
            int r0 = w * 16 + gid;
            u32 a0 = sbase + Po + r0 * 256 + ((ch ^ (r0 & 7)) << 4) + (tig & 1) * 8;
            STS2(a0, f2tf32(e0), f2tf32(e1));
            int r1 = r0 + 8;
            u32 a1 = sbase + Po + r1 * 256 + ((ch ^ (r1 & 7)) << 4) + (tig & 1) * 8;
            STS2(a1, f2tf32(e2), f2tf32(e3));
        }
        __syncwarp();   // P rows are warp-private; only this warp reads them

        // ---- O += P V (kt-outer over 64 tokens) ----
#pragma unroll
        for (int kt = 0; kt < 8; kt++) {
            u32 A[4];
            {
                int r = arow0;
                u32 a = sbase + Po + r * 256 + (((kt * 2 + ahi) ^ (r & 7)) << 4);
                LDSM4(A, a);
            }
#pragma unroll
            for (int nbp = 0; nbp < 4; nbp++) {
                int rr = nbp * 16 + brow8;
                u32 ab = sbase + Vob[cur] + rr * 256 + (((kt * 2 + bhi) ^ (rr & 7)) << 4);
                u32 B[4]; LDSM4(B, ab);
                mma_tf32(oc[nbp*2],   A[0], A[1], A[2], A[3], B[0], B[1]);
                mma_tf32(oc[nbp*2+1], A[0], A[1], A[2], A[3], B[2], B[3]);
            }
        }
        __syncwarp();   // this warp's P reads done before next-iter P writes
    }

    // ---- reduce l across tig lanes (warp-local rows) ----
#pragma unroll
    for (int i = 0; i < 2; i++) {
        lsum[i] += __shfl_xor_sync(~0u, lsum[i], 1);
        lsum[i] += __shfl_xor_sync(~0u, lsum[i], 2);
    }
    float inv0 = 1.f / lsum[0];
    float inv1 = 1.f / lsum[1];

    // ---- epilogue ----
    float* xb = g_x + ((size_t)b * DD + h) * NN;
    int r0 = q0 + w * 16 + gid;
    int r1 = r0 + 8;
#pragma unroll
    for (int nb = 0; nb < 8; nb++) {
        int dd0 = nb * 8 + tig * 2;
        xb[(size_t)dd0 * (NH * NN) + r0]       = oc[nb][0] * inv0;
        xb[(size_t)(dd0 + 1) * (NH * NN) + r0] = oc[nb][1] * inv0;
        xb[(size_t)dd0 * (NH * NN) + r1]       = oc[nb][2] * inv1;
        xb[(size_t)(dd0 + 1) * (NH * NN) + r1] = oc[nb][3] * inv1;
    }
}

// ---------------------------------------------------------------------------
extern "C" void kernel_launch(void* const* d_in, const int* in_sizes, int n_in,
                              void* d_out, int out_size)
{
    const float* query = (const float*)d_in[0];
    const float* key_  = (const float*)d_in[1];
    const float* value = (const float*)d_in[2];
    const int*   mask  = (const int*)  d_in[3];
    const float* Wq = (const float*)d_in[4];
    const float* bq = (const float*)d_in[5];
    const float* Wk = (const float*)d_in[6];
    const float* bk = (const float*)d_in[7];
    const float* Wv = (const float*)d_in[8];
    const float* bv = (const float*)d_in[9];
    const float* Wm = (const float*)d_in[10];
    const float* bm = (const float*)d_in[11];
    float* out = (float*)d_out;

    float *q, *k, *v, *x;
    cudaGetSymbolAddress((void**)&q, g_q);
    cudaGetSymbolAddress((void**)&k, g_k);
    cudaGetSymbolAddress((void**)&v, g_v);
    cudaGetSymbolAddress((void**)&x, g_x);

    const int psmem = 49152;
    cudaFuncSetAttribute(qkv_proj, cudaFuncAttributeMaxDynamicSharedMemorySize, psmem);
    dim3 qkvgrid(NN / 64, DD / 128, 3 * BB);
    qkv_proj<<<qkvgrid, 256, psmem>>>(Wq, bq, query, Wk, bk, key_, Wv, bv, value, q, k, v);

    const int asmem = 106496;
    cudaFuncSetAttribute(attn_mma, cudaFuncAttributeMaxDynamicSharedMemorySize, asmem);
    dim3 agrid(NN / QTILE, NH, BB);
    attn_mma<<<agrid, 256, asmem>>>(mask);

    const int osmem = 98304;
    cudaFuncSetAttribute(proj_out3, cudaFuncAttributeMaxDynamicSharedMemorySize, osmem);
    dim3 pmgrid(NN / 64, DD / 128, BB);
    proj_out3<<<pmgrid, 256, osmem>>>(Wm, bm, x, out);
}

// round 16
// speedup vs baseline: 1.0517x; 1.0517x over previous
#include <cuda_runtime.h>
#include <math.h>
#include <stdint.h>

#define BB 8
#define DD 256
#define NN 2048
#define NH 4
#define HD 64
#define QTILE 128

typedef unsigned long long u64;
typedef unsigned int u32;

// Scratch. g_q/g_k TRANSPOSED per-head [b][h][tok][dd] (tf32 bits, q pre-scaled);
// g_v natural [b][ch][tok] (tf32 bits); g_x natural fp32.
__device__ float g_q[BB*DD*NN];
__device__ float g_k[BB*DD*NN];
__device__ float g_v[BB*DD*NN];
__device__ float g_x[BB*DD*NN];
// Pre-converted, pre-swizzled W tiles: [p(3)][oblk(2)][kc(4)] x 8192 u32
__device__ u32 g_wt[24 * 8192];

__device__ __forceinline__ u32 f2tf32(float x) {
    u32 r; asm("cvt.rna.tf32.f32 %0, %1;" : "=r"(r) : "f"(x)); return r;
}
__device__ __forceinline__ u32 smem_u32(const void* p) {
    u32 a; asm("{ .reg .u64 t; cvta.to.shared.u64 t, %1; cvt.u32.u64 %0, t; }" : "=r"(a) : "l"(p));
    return a;
}
__device__ __forceinline__ void mma_tf32(float c[4], u32 a0, u32 a1, u32 a2, u32 a3,
                                         u32 b0, u32 b1) {
    asm volatile("mma.sync.aligned.m16n8k8.row.col.f32.tf32.tf32.f32 "
        "{%0,%1,%2,%3}, {%4,%5,%6,%7}, {%8,%9}, {%0,%1,%2,%3};"
        : "+f"(c[0]), "+f"(c[1]), "+f"(c[2]), "+f"(c[3])
        : "r"(a0), "r"(a1), "r"(a2), "r"(a3), "r"(b0), "r"(b1));
}
#define LDSM4(r, a) asm volatile( \
    "ldmatrix.sync.aligned.m8n8.x4.shared.b16 {%0,%1,%2,%3}, [%4];" \
    : "=r"((r)[0]), "=r"((r)[1]), "=r"((r)[2]), "=r"((r)[3]) : "r"(a))
#define STS2(a, x, y) asm volatile( \
    "st.shared.v2.b32 [%0], {%1,%2};" :: "r"(a), "r"(x), "r"(y) : "memory")
#define STS4(a, x, y, z, w_) asm volatile( \
    "st.shared.v4.b32 [%0], {%1,%2,%3,%4};" :: "r"(a), "r"(x), "r"(y), "r"(z), "r"(w_) : "memory")
#define CPA16(dst, src) asm volatile( \
    "cp.async.cg.shared.global [%0], [%1], 16;" :: "r"(dst), "l"(src) : "memory")
#define CPA_COMMIT() asm volatile("cp.async.commit_group;" ::: "memory")
#define CPA_WAIT0()  asm volatile("cp.async.wait_group 0;" ::: "memory")
#define CPA_WAIT1()  asm volatile("cp.async.wait_group 1;" ::: "memory")

// ---------------------------------------------------------------------------
// prep_w: convert W to tf32 (cvt.rna, identical to the old in-kernel path) and
// store the exact swizzled smem image of each [128 o][64 i] tile.
// blockIdx.x = (p*2 + oblk)*4 + kc.
// image u32 index: row*64 + ((c ^ (row&7))<<2) + e,  c=chunk(16B), e=0..3
// ---------------------------------------------------------------------------
__global__ void prep_w(const float* __restrict__ Wq, const float* __restrict__ Wk,
                       const float* __restrict__ Wv)
{
    int blk = blockIdx.x;
    int kc = blk & 3, ob = (blk >> 2) & 1, p = blk >> 3;
    const float* W = (p == 0) ? Wq : (p == 1) ? Wk : Wv;
    u32* dst = g_wt + blk * 8192;
    for (int i = threadIdx.x; i < 8192; i += blockDim.x) {
        int row = i >> 6;            // 0..127
        int c = (i >> 2) & 15;       // source chunk
        int e = i & 3;
        float v = W[(size_t)(ob * 128 + row) * DD + kc * 64 + c * 4 + e];
        dst[row * 64 + ((c ^ (row & 7)) << 2) + e] = f2tf32(v);
    }
}

// ---------------------------------------------------------------------------
// Merged tf32 mma projection for q/k/v, v2: W via double-buffered cp.async
// from pre-swizzled g_wt; X^T fill double-buffered (LDG+cvt+STS).
// blockIdx.z = p*BB + b. Warps 4(m over o) x 2(n over tok).
// SMEM: A[2] 32KB @0/32768, B[2] 16KB @65536/81920. Total 96KB, 2 CTAs/SM.
// ---------------------------------------------------------------------------
__global__ __launch_bounds__(256, 2) void qkv_proj(
    const float* __restrict__ Xq, const float* __restrict__ Xk, const float* __restrict__ Xv,
    const float* __restrict__ bq, const float* __restrict__ bk, const float* __restrict__ bv,
    float* __restrict__ Yq, float* __restrict__ Yk, float* __restrict__ Yv)
{
    extern __shared__ u32 psm[];
    const u32 sbase = smem_u32(psm);
    const u32 Ab[2] = {0u, 32768u};
    const u32 Bb[2] = {65536u, 81920u};

    const int t = threadIdx.x;
    const int w = t >> 5, lane = t & 31;
    const int wm = w >> 1, wn = w & 1;
    const int gid = lane >> 2, tig = lane & 3;
    const int p  = blockIdx.z >> 3;
    const int b  = blockIdx.z & 7;
    const int o0 = blockIdx.y * 128;
    const int n0 = blockIdx.x * 64;

    const float *X, *bias;
    float* Y;
    if (p == 0)      { X = Xq; bias = bq; Y = Yq; }
    else if (p == 1) { X = Xk; bias = bk; Y = Yk; }
    else             { X = Xv; bias = bv; Y = Yv; }

    const u32* wt = g_wt + ((p * 2 + blockIdx.y) * 4) * 8192;

    const int arow0 = wm * 32 + (lane & 15);
    const int ahi = lane >> 4;
    const int brow8 = ((lane >> 4) << 3) + (lane & 7);
    const int bhi = (lane >> 3) & 1;

    const float* Xb = X + (size_t)b * DD * NN;

    float oc[2][4][4];
#pragma unroll
    for (int mi = 0; mi < 2; mi++)
#pragma unroll
        for (int nb = 0; nb < 4; nb++)
#pragma unroll
            for (int e = 0; e < 4; e++) oc[mi][nb][e] = 0.f;

    // ---- prologue: W chunk0 via cp.async, X chunk0 via LDG/STS ----
#pragma unroll
    for (int i = 0; i < 8; i++) {
        int idx = t + i * 256;  // 2048 CPA16 total
        CPA16(sbase + Ab[0] + idx * 16, wt + idx * 4);
    }
    CPA_COMMIT();
#pragma unroll
    for (int i = 0; i < 4; i++) {
        int idx = t + i * 256;
        int tok = idx & 63, kq = idx >> 6;
        const float* src = Xb + (size_t)(kq * 4) * NN + n0 + tok;
        u32 v0 = f2tf32(src[0]);
        u32 v1 = f2tf32(src[NN]);
        u32 v2 = f2tf32(src[2 * NN]);
        u32 v3 = f2tf32(src[3 * NN]);
        STS4(sbase + Bb[0] + tok * 256 + ((kq ^ (tok & 7)) << 4), v0, v1, v2, v3);
    }

    for (int kc = 0; kc < 4; kc++) {
        const int cur = kc & 1;
        __syncthreads();   // compute(kc-1) done reading buffers we refill; X STS ordering
        if (kc + 1 < 4) {
#pragma unroll
            for (int i = 0; i < 8; i++) {
                int idx = t + i * 256;
                CPA16(sbase + Ab[1 - cur] + idx * 16, wt + (kc + 1) * 8192 + idx * 4);
            }
            CPA_COMMIT();
#pragma unroll
            for (int i = 0; i < 4; i++) {
                int idx = t + i * 256;
                int tok = idx & 63, kq = idx >> 6;
                const float* src = Xb + (size_t)((kc + 1) * 64 + kq * 4) * NN + n0 + tok;
                u32 v0 = f2tf32(src[0]);
                u32 v1 = f2tf32(src[NN]);
                u32 v2 = f2tf32(src[2 * NN]);
                u32 v3 = f2tf32(src[3 * NN]);
                STS4(sbase + Bb[1 - cur] + tok * 256 + ((kq ^ (tok & 7)) << 4), v0, v1, v2, v3);
            }
            CPA_WAIT1();   // W(cur) landed; W(kc+1) may still fly
        } else {
            CPA_WAIT0();
        }
        __syncthreads();   // W(cur) + X(cur) visible to all warps

#pragma unroll
        for (int ks = 0; ks < 8; ks++) {
            u32 A0[4], A1[4];
            {
                int r = arow0;
                u32 a = sbase + Ab[cur] + r * 256 + (((ks * 2 + ahi) ^ (r & 7)) << 4);
                LDSM4(A0, a);
                r = arow0 + 16;
                a = sbase + Ab[cur] + r * 256 + (((ks * 2 + ahi) ^ (r & 7)) << 4);
                LDSM4(A1, a);
            }
#pragma unroll
            for (int nbp = 0; nbp < 2; nbp++) {
                int rr = wn * 32 + nbp * 16 + brow8;
                u32 ab = sbase + Bb[cur] + rr * 256 + (((ks * 2 + bhi) ^ (rr & 7)) << 4);
                u32 B[4]; LDSM4(B, ab);
                mma_tf32(oc[0][nbp*2],   A0[0], A0[1], A0[2], A0[3], B[0], B[1]);
                mma_tf32(oc[1][nbp*2],   A1[0], A1[1], A1[2], A1[3], B[0], B[1]);
                mma_tf32(oc[0][nbp*2+1], A0[0], A0[1], A0[2], A0[3], B[2], B[3]);
                mma_tf32(oc[1][nbp*2+1], A1[0], A1[1], A1[2], A1[3], B[2], B[3]);
            }
        }
    }

    const float scl = (p == 0) ? 0.125f : 1.0f;
    float bv2[2][2];
#pragma unroll
    for (int mi = 0; mi < 2; mi++) {
        bv2[mi][0] = bias[o0 + wm * 32 + mi * 16 + gid];
        bv2[mi][1] = bias[o0 + wm * 32 + mi * 16 + gid + 8];
    }
#pragma unroll
    for (int mi = 0; mi < 2; mi++)
#pragma unroll
    for (int nb = 0; nb < 4; nb++) {
        int token = n0 + wn * 32 + nb * 8 + tig * 2;
        u32 t0 = f2tf32((oc[mi][nb][0] + bv2[mi][0]) * scl);
        u32 t1 = f2tf32((oc[mi][nb][1] + bv2[mi][0]) * scl);
        u32 t2 = f2tf32((oc[mi][nb][2] + bv2[mi][1]) * scl);
        u32 t3 = f2tf32((oc[mi][nb][3] + bv2[mi][1]) * scl);
        int o = o0 + wm * 32 + mi * 16 + gid;
        if (p < 2) {
            {
                float* d = Y + (((size_t)b * NH + (o & 3)) * NN + token) * HD + (o >> 2);
                d[0]  = __uint_as_float(t0);
                d[HD] = __uint_as_float(t1);
            }
            {
                int o2 = o + 8;
                float* d = Y + (((size_t)b * NH + (o2 & 3)) * NN + token) * HD + (o2 >> 2);
                d[0]  = __uint_as_float(t2);
                d[HD] = __uint_as_float(t3);
            }
        } else {
            *(float2*)&Y[((size_t)b * DD + o) * NN + token] =
                make_float2(__uint_as_float(t0), __uint_as_float(t1));
            *(float2*)&Y[((size_t)b * DD + o + 8) * NN + token] =
                make_float2(__uint_as_float(t2), __uint_as_float(t3));
        }
    }
}

// ---------------------------------------------------------------------------
// 3xTF32 output projection (fp32-accurate) — unchanged (R13 proven).
// ---------------------------------------------------------------------------
__global__ __launch_bounds__(256, 2) void proj_out3(
    const float* __restrict__ W, const float* __restrict__ bias,
    const float* __restrict__ X, float* __restrict__ Y)
{
    extern __shared__ u32 psm[];
    const u32 sbase = smem_u32(psm);
    const u32 Ahi = 0, Alo = 32768, Bhi = 65536, Blo = 81920;

    const int t = threadIdx.x;
    const int w = t >> 5, lane = t & 31;
    const int wm = w >> 1, wn = w & 1;
    const int gid = lane >> 2, tig = lane & 3;
    const int b  = blockIdx.z;
    const int o0 = blockIdx.y * 128;
    const int n0 = blockIdx.x * 64;

    const int arow0 = wm * 32 + (lane & 15);
    const int ahi = lane >> 4;
    const int brow8 = ((lane >> 4) << 3) + (lane & 7);
    const int bhi = (lane >> 3) & 1;

    const float* Xb = X + (size_t)b * DD * NN;

    float oc[2][4][4];
#pragma unroll
    for (int mi = 0; mi < 2; mi++)
#pragma unroll
        for (int nb = 0; nb < 4; nb++)
#pragma unroll
            for (int e = 0; e < 4; e++) oc[mi][nb][e] = 0.f;

    for (int kc = 0; kc < DD; kc += 64) {
        __syncthreads();
#pragma unroll
        for (int i = 0; i < 8; i++) {
            int idx = t + i * 256;
            int row = idx >> 4, c = idx & 15;
            float4 wv = *(const float4*)&W[(size_t)(o0 + row) * DD + kc + c * 4];
            u32 h0 = f2tf32(wv.x), h1 = f2tf32(wv.y), h2 = f2tf32(wv.z), h3 = f2tf32(wv.w);
            u32 l0 = f2tf32(wv.x - __uint_as_float(h0));
            u32 l1 = f2tf32(wv.y - __uint_as_float(h1));
            u32 l2 = f2tf32(wv.z - __uint_as_float(h2));
            u32 l3 = f2tf32(wv.w - __uint_as_float(h3));
            u32 off = row * 256 + ((c ^ (row & 7)) << 4);
            STS4(sbase + Ahi + off, h0, h1, h2, h3);
            STS4(sbase + Alo + off, l0, l1, l2, l3);
        }
#pragma unroll
        for (int i = 0; i < 4; i++) {
            int idx = t + i * 256;
            int tok = idx & 63, kq = idx >> 6;
            const float* src = Xb + (size_t)(kc + kq * 4) * NN + n0 + tok;
            float x0 = src[0], x1 = src[NN], x2 = src[2 * NN], x3 = src[3 * NN];
            u32 h0 = f2tf32(x0), h1 = f2tf32(x1), h2 = f2tf32(x2), h3 = f2tf32(x3);
            u32 l0 = f2tf32(x0 - __uint_as_float(h0));
            u32 l1 = f2tf32(x1 - __uint_as_float(h1));
            u32 l2 = f2tf32(x2 - __uint_as_float(h2));
            u32 l3 = f2tf32(x3 - __uint_as_float(h3));
            u32 off = tok * 256 + ((kq ^ (tok & 7)) << 4);
            STS4(sbase + Bhi + off, h0, h1, h2, h3);
            STS4(sbase + Blo + off, l0, l1, l2, l3);
        }
        __syncthreads();

        const u32 Ap[3] = {Ahi, Alo, Ahi};
        const u32 Bp[3] = {Bhi, Bhi, Blo};
#pragma unroll
        for (int pass = 0; pass < 3; pass++) {
#pragma unroll
            for (int ks = 0; ks < 8; ks++) {
                u32 A0[4], A1[4];
                {
                    int r = arow0;
                    u32 a = sbase + Ap[pass] + r * 256 + (((ks * 2 + ahi) ^ (r & 7)) << 4);
                    LDSM4(A0, a);
                    r = arow0 + 16;
                    a = sbase + Ap[pass] + r * 256 + (((ks * 2 + ahi) ^ (r & 7)) << 4);
                    LDSM4(A1, a);
                }
#pragma unroll
                for (int nbp = 0; nbp < 2; nbp++) {
                    int rr = wn * 32 + nbp * 16 + brow8;
                    u32 ab = sbase + Bp[pass] + rr * 256 + (((ks * 2 + bhi) ^ (rr & 7)) << 4);
                    u32 B[4]; LDSM4(B, ab);
                    mma_tf32(oc[0][nbp*2],   A0[0], A0[1], A0[2], A0[3], B[0], B[1]);
                    mma_tf32(oc[1][nbp*2],   A1[0], A1[1], A1[2], A1[3], B[0], B[1]);
                    mma_tf32(oc[0][nbp*2+1], A0[0], A0[1], A0[2], A0[3], B[2], B[3]);
                    mma_tf32(oc[1][nbp*2+1], A1[0], A1[1], A1[2], A1[3], B[2], B[3]);
                }
            }
        }
    }

    float bv[2][2];
#pragma unroll
    for (int mi = 0; mi < 2; mi++) {
        bv[mi][0] = bias[o0 + wm * 32 + mi * 16 + gid];
        bv[mi][1] = bias[o0 + wm * 32 + mi * 16 + gid + 8];
    }
#pragma unroll
    for (int mi = 0; mi < 2; mi++)
#pragma unroll
    for (int nb = 0; nb < 4; nb++) {
        int token = n0 + wn * 32 + nb * 8 + tig * 2;
        int o = o0 + wm * 32 + mi * 16 + gid;
        *(float2*)&Y[((size_t)b * DD + o) * NN + token] =
            make_float2(oc[mi][nb][0] + bv[mi][0], oc[mi][nb][1] + bv[mi][0]);
        *(float2*)&Y[((size_t)b * DD + o + 8) * NN + token] =
            make_float2(oc[mi][nb][2] + bv[mi][1], oc[mi][nb][3] + bv[mi][1]);
    }
}

// ---------------------------------------------------------------------------
// mma.sync tf32 flash attention — R13 kernel verbatim (measured 249 us).
// 256 threads, 2 CTA/SM, KTILE=32 double-buffered cp.async pipeline.
// ---------------------------------------------------------------------------
__global__ __launch_bounds__(256, 2) void attn_mma(const int* __restrict__ mask)
{
    extern __shared__ u32 smu[];
    const u32 sbase = smem_u32(smu);
    const u32 Qo = 0;
    const u32 Kob[2] = {32768u, 40960u};
    const u32 Vob[2] = {49152u, 57344u};
    const u32 Po = 65536;
    float* sMask = (float*)(smu + 20480);
    float* sL = (float*)(smu + 22528);

    const int t = threadIdx.x;
    const int w = t >> 5, lane = t & 31;
    const int wm = w >> 1, wn = w & 1;
    const int gid = lane >> 2, tig = lane & 3;
    const int b = blockIdx.z, h = blockIdx.y;
    const int q0 = blockIdx.x * QTILE;

    const int arow0 = wm * 32 + (lane & 15);
    const int ahi = lane >> 4;
    const int brow8 = ((lane >> 4) << 3) + (lane & 7);
    const int bhi = (lane >> 3) & 1;

    const float* qb = g_q + (((size_t)b * NH + h) * NN + q0) * HD;
    const float* kb0 = g_k + (((size_t)b * NH + h) * NN) * HD;
    const float* vb0 = g_v + ((size_t)b * DD + h) * NN;
    const int* mb_ = mask + (size_t)b * NN;

    // ---- prologue: Q fill + mask fill + tile0 fill, one commit group ----
#pragma unroll
    for (int i = 0; i < 2; i++) {
        int idx = t + i * 256;
        int row = idx >> 2, c4 = (idx & 3) * 4;
#pragma unroll
        for (int j = 0; j < 4; j++) {
            int c = c4 + j;
            u32 a = sbase + Qo + row * 256 + ((c ^ (row & 7)) << 4);
            CPA16(a, qb + row * HD + c * 4);
        }
    }
#pragma unroll
    for (int i = 0; i < 8; i++) {
        int j = t + i * 256;
        sMask[j] = (float)mb_[j];
    }
#pragma unroll
    for (int i = 0; i < 2; i++) {
        int idx = t + i * 256;
        int row = idx >> 4, c = idx & 15;
        u32 a = sbase + Kob[0] + row * 256 + ((c ^ (row & 7)) << 4);
        CPA16(a, kb0 + (size_t)row * HD + c * 4);
    }
#pragma unroll
    for (int i = 0; i < 2; i++) {
        int idx = t + i * 256;
        int dd = idx >> 3, c = idx & 7;
        u32 a = sbase + Vob[0] + dd * 128 + ((c ^ (dd & 7)) << 4);
        CPA16(a, vb0 + (size_t)dd * (NH * NN) + c * 4);
    }
    CPA_COMMIT();

    float qmf[4];
    qmf[0] = (float)mb_[q0 + wm * 32 + gid];
    qmf[1] = (float)mb_[q0 + wm * 32 + gid + 8];
    qmf[2] = (float)mb_[q0 + wm * 32 + gid + 16];
    qmf[3] = (float)mb_[q0 + wm * 32 + gid + 24];

    float oc[2][4][4];
#pragma unroll
    for (int mi = 0; mi < 2; mi++)
#pragma unroll
        for (int nb = 0; nb < 4; nb++)
#pragma unroll
            for (int e = 0; e < 4; e++) oc[mi][nb][e] = 0.f;
    float lsum[4] = {0.f, 0.f, 0.f, 0.f};

    for (int it = 0; it < 64; it++) {
        const int k0 = it * 32;
        const int cur = it & 1;
        __syncthreads();
        if (it + 1 < 64) {
            const int nxt = 1 - cur;
            const int k0n = k0 + 32;
#pragma unroll
            for (int i = 0; i < 2; i++) {
                int idx = t + i * 256;
                int row = idx >> 4, c = idx & 15;
                u32 a = sbase + Kob[nxt] + row * 256 + ((c ^ (row & 7)) << 4);
                CPA16(a, kb0 + (size_t)(k0n + row) * HD + c * 4);
            }
#pragma unroll
            for (int i = 0; i < 2; i++) {
                int idx = t + i * 256;
                int dd = idx >> 3, c = idx & 7;
                u32 a = sbase + Vob[nxt] + dd * 128 + ((c ^ (dd & 7)) << 4);
                CPA16(a, vb0 + (size_t)dd * (NH * NN) + k0n + c * 4);
            }
            CPA_COMMIT();
            CPA_WAIT1();
        } else {
            CPA_WAIT0();
        }
        __syncthreads();

        // ---- S = Q K^T (warp: 32 q x 16 k) ----
        float sc[2][2][4];
#pragma unroll
        for (int mi = 0; mi < 2; mi++)
#pragma unroll
            for (int nb = 0; nb < 2; nb++)
#pragma unroll
                for (int e = 0; e < 4; e++) sc[mi][nb][e] = 0.f;
#pragma unroll
        for (int ks = 0; ks < 8; ks++) {
            u32 A0[4], A1[4];
            {
                int r = arow0;
                u32 a = sbase + Qo + r * 256 + (((ks * 2 + ahi) ^ (r & 7)) << 4);
                LDSM4(A0, a);
                r = arow0 + 16;
                a = sbase + Qo + r * 256 + (((ks * 2 + ahi) ^ (r & 7)) << 4);
                LDSM4(A1, a);
            }
            int rr = wn * 16 + brow8;
            u32 ab = sbase + Kob[cur] + rr * 256 + (((ks * 2 + bhi) ^ (rr & 7)) << 4);
            u32 B[4]; LDSM4(B, ab);
            mma_tf32(sc[0][0], A0[0], A0[1], A0[2], A0[3], B[0], B[1]);
            mma_tf32(sc[1][0], A1[0], A1[1], A1[2], A1[3], B[0], B[1]);
            mma_tf32(sc[0][1], A0[0], A0[1], A0[2], A0[3], B[2], B[3]);
            mma_tf32(sc[1][1], A1[0], A1[1], A1[2], A1[3], B[2], B[3]);
        }

        // ---- softmax (no-max, multiply-mask), P -> sP ----
#pragma unroll
        for (int nb = 0; nb < 2; nb++) {
            int col0 = wn * 16 + nb * 8 + tig * 2;
            float km0 = sMask[k0 + col0], km1 = sMask[k0 + col0 + 1];
            float e0 = __expf(sc[0][nb][0]) * qmf[0] * km0;
            float e1 = __expf(sc[0][nb][1]) * qmf[0] * km1;
            float e2 = __expf(sc[0][nb][2]) * qmf[1] * km0;
            float e3 = __expf(sc[0][nb][3]) * qmf[1] * km1;
            float f0 = __expf(sc[1][nb][0]) * qmf[2] * km0;
            float f1 = __expf(sc[1][nb][1]) * qmf[2] * km1;
            float f2 = __expf(sc[1][nb][2]) * qmf[3] * km0;
            float f3 = __expf(sc[1][nb][3]) * qmf[3] * km1;
            lsum[0] += e0 + e1; lsum[1] += e2 + e3;
            lsum[2] += f0 + f1; lsum[3] += f2 + f3;
            int ch = col0 >> 2;
            int r0 = wm * 32 + gid;
            u32 a0 = sbase + Po + r0 * 128 + ((ch ^ (r0 & 7)) << 4) + (tig & 1) * 8;
            STS2(a0, f2tf32(e0), f2tf32(e1));
            int r1 = r0 + 8;
            u32 a1 = sbase + Po + r1 * 128 + ((ch ^ (r1 & 7)) << 4) + (tig & 1) * 8;
            STS2(a1, f2tf32(e2), f2tf32(e3));
            int r2 = r0 + 16;
            u32 a2 = sbase + Po + r2 * 128 + ((ch ^ (r2 & 7)) << 4) + (tig & 1) * 8;
            STS2(a2, f2tf32(f0), f2tf32(f1));
            int r3 = r0 + 24;
            u32 a3 = sbase + Po + r3 * 128 + ((ch ^ (r3 & 7)) << 4) + (tig & 1) * 8;
            STS2(a3, f2tf32(f2), f2tf32(f3));
        }
        __syncthreads();

        // ---- O += P V (kt 0..3 over 32 tokens) ----
#pragma unroll
        for (int kt = 0; kt < 4; kt++) {
            u32 A0[4], A1[4];
            {
                int r = arow0;
                u32 a = sbase + Po + r * 128 + (((kt * 2 + ahi) ^ (r & 7)) << 4);
                LDSM4(A0, a);
                r = arow0 + 16;
                a = sbase + Po + r * 128 + (((kt * 2 + ahi) ^ (r & 7)) << 4);
                LDSM4(A1, a);
            }
#pragma unroll
            for (int nbp = 0; nbp < 2; nbp++) {
                int rr = wn * 32 + nbp * 16 + brow8;
                u32 ab = sbase + Vob[cur] + rr * 128 + (((kt * 2 + bhi) ^ (rr & 7)) << 4);
                u32 B[4]; LDSM4(B, ab);
                mma_tf32(oc[0][nbp*2],   A0[0], A0[1], A0[2], A0[3], B[0], B[1]);
                mma_tf32(oc[1][nbp*2],   A1[0], A1[1], A1[2], A1[3], B[0], B[1]);
                mma_tf32(oc[0][nbp*2+1], A0[0], A0[1], A0[2], A0[3], B[2], B[3]);
                mma_tf32(oc[1][nbp*2+1], A1[0], A1[1], A1[2], A1[3], B[2], B[3]);
            }
        }
    }

    // ---- reduce l, epilogue ----
#pragma unroll
    for (int i = 0; i < 4; i++) {
        lsum[i] += __shfl_xor_sync(~0u, lsum[i], 1);
        lsum[i] += __shfl_xor_sync(~0u, lsum[i], 2);
    }
    if (tig == 0) {
        sL[wn * 128 + wm * 32 + gid]      = lsum[0];
        sL[wn * 128 + wm * 32 + gid + 8]  = lsum[1];
        sL[wn * 128 + wm * 32 + gid + 16] = lsum[2];
        sL[wn * 128 + wm * 32 + gid + 24] = lsum[3];
    }
    __syncthreads();
    float inv[4];
#pragma unroll
    for (int i = 0; i < 4; i++) {
        int rl = wm * 32 + ((i & 1) ? 8 : 0) + ((i >> 1) ? 16 : 0) + gid;
        inv[i] = 1.f / (sL[rl] + sL[128 + rl]);
    }

    float* xb = g_x + ((size_t)b * DD + h) * NN;
#pragma unroll
    for (int mi = 0; mi < 2; mi++) {
        int r0 = q0 + wm * 32 + mi * 16 + gid;
        int r1 = r0 + 8;
#pragma unroll
        for (int nb = 0; nb < 4; nb++) {
            int dd0 = wn * 32 + nb * 8 + tig * 2;
            xb[(size_t)dd0 * (NH * NN) + r0]       = oc[mi][nb][0] * inv[2*mi];
            xb[(size_t)(dd0 + 1) * (NH * NN) + r0] = oc[mi][nb][1] * inv[2*mi];
            xb[(size_t)dd0 * (NH * NN) + r1]       = oc[mi][nb][2] * inv[2*mi+1];
            xb[(size_t)(dd0 + 1) * (NH * NN) + r1] = oc[mi][nb][3] * inv[2*mi+1];
        }
    }
}

// ---------------------------------------------------------------------------
extern "C" void kernel_launch(void* const* d_in, const int* in_sizes, int n_in,
                              void* d_out, int out_size)
{
    const float* query = (const float*)d_in[0];
    const float* key_  = (const float*)d_in[1];
    const float* value = (const float*)d_in[2];
    const int*   mask  = (const int*)  d_in[3];
    const float* Wq = (const float*)d_in[4];
    const float* bq = (const float*)d_in[5];
    const float* Wk = (const float*)d_in[6];
    const float* bk = (const float*)d_in[7];
    const float* Wv = (const float*)d_in[8];
    const float* bv = (const float*)d_in[9];
    const float* Wm = (const float*)d_in[10];
    const float* bm = (const float*)d_in[11];
    float* out = (float*)d_out;

    float *q, *k, *v, *x;
    cudaGetSymbolAddress((void**)&q, g_q);
    cudaGetSymbolAddress((void**)&k, g_k);
    cudaGetSymbolAddress((void**)&v, g_v);
    cudaGetSymbolAddress((void**)&x, g_x);

    prep_w<<<24, 256>>>(Wq, Wk, Wv);

    const int psmem = 98304;
    cudaFuncSetAttribute(qkv_proj, cudaFuncAttributeMaxDynamicSharedMemorySize, psmem);
    dim3 qkvgrid(NN / 64, DD / 128, 3 * BB);
    qkv_proj<<<qkvgrid, 256, psmem>>>(query, key_, value, bq, bk, bv, q, k, v);

    const int asmem = 91136 + 1024;
    cudaFuncSetAttribute(attn_mma, cudaFuncAttributeMaxDynamicSharedMemorySize, asmem);
    dim3 agrid(NN / QTILE, NH, BB);
    attn_mma<<<agrid, 256, asmem>>>(mask);

    const int osmem = 98304;
    cudaFuncSetAttribute(proj_out3, cudaFuncAttributeMaxDynamicSharedMemorySize, osmem);
    dim3 pmgrid(NN / 64, DD / 128, BB);
    proj_out3<<<pmgrid, 256, osmem>>>(Wm, bm, x, out);
}